// round 14
// baseline (speedup 1.0000x reference)
#include <cuda_runtime.h>
#include <cuda_fp16.h>
#include <cstdint>

#define TPB 128

namespace {
constexpr int Cn = 64, Hn = 112, Wn = 112, Fn = 128;
constexpr int PIX   = Hn * Wn;           // 12544
constexpr int XW    = 36;                // words per (row,xp): 32 half2 data + 4 pad
constexpr int ROWXP = 120;               // xp per row (halo 3..116 used)
constexpr int SIN_W = 4 * ROWXP * XW;    // 17280 words (4 rows)
constexpr int BPT   = 5120;              // packed-B words per tap
constexpr int SMEM_WORDS = SIN_W + 2 * BPT;  // 27520
constexpr int SMEM_BYTES = SMEM_WORDS * 4;   // 110080
}

// fragment-packed fp16 weights: [tap][s(4)][wnIdx(2)][lane(32)][20] (16 used + 4 pad)
__device__ __align__(16) uint32_t g_wt[9 * BPT];

__device__ __forceinline__ uint32_t smem_u32(const void* p) {
    uint32_t a;
    asm("{ .reg .u64 t; cvta.to.shared.u64 t, %1; cvt.u32.u64 %0, t; }" : "=r"(a) : "l"(p));
    return a;
}
__device__ __forceinline__ void cpa16(uint32_t dst, const void* src) {
    asm volatile("cp.async.cg.shared.global [%0], [%1], 16;"
                 :: "r"(dst), "l"(src));
}
#define CP_COMMIT() asm volatile("cp.async.commit_group;" ::: "memory")
#define CP_WAIT0()  asm volatile("cp.async.wait_group 0;"  ::: "memory")

__device__ __forceinline__ void ldsm_x4(uint32_t a[4], uint32_t addr) {
    asm volatile("ldmatrix.sync.aligned.m8n8.x4.shared.b16 {%0,%1,%2,%3}, [%4];"
                 : "=r"(a[0]), "=r"(a[1]), "=r"(a[2]), "=r"(a[3]) : "r"(addr));
}

// build fp16 fragment-packed B for m16n8k16 (same as R13)
__global__ void pack_wt_h_kernel(const float* __restrict__ wt) {
    int i = blockIdx.x * 256 + threadIdx.x;
    if (i >= 9 * BPT) return;
    int w     = i % 20;
    int j     = i / 20;
    int lane  = j % 32;
    int t     = j / 32;
    int wnIdx = t % 2;
    int t2    = t / 2;
    int s     = t2 % 4;
    int tap   = t2 / 4;
    uint32_t val = 0;
    if (w < 16) {
        int ni    = w >> 1;
        int which = w & 1;                  // 0 -> k 0..7, 1 -> k 8..15
        int l3    = lane & 3;
        int f  = wnIdx * 64 + ni * 8 + (lane >> 2);
        int c0 = s * 16 + which * 8 + 2 * l3;
        float v0 = wt[f * 576 + c0 * 9 + tap];
        float v1 = wt[f * 576 + (c0 + 1) * 9 + tap];
        __half2 h = __floats2half2_rn(v0, v1);  // low = even k
        val = *(uint32_t*)&h;
    }
    g_wt[i] = val;
}

// D[m=128 pixels][n=128 filters]; 4 warps 64x64; x-major A + ldmatrix
__global__ void __launch_bounds__(TPB, 2)
conv_hmma2_kernel(const float* __restrict__ in, float* __restrict__ out)
{
    extern __shared__ uint32_t smem[];
    const uint32_t sbase = smem_u32(smem);

    const int tid  = threadIdx.x;
    const int lane = tid & 31;
    const int wid  = tid >> 5;          // 0..3
    const int wnIdx = wid >> 1;         // 0 or 1
    const int bb   = blockIdx.y;
    const int p0   = blockIdx.x * 128;
    const int py0  = p0 / Wn;
    const int px0  = p0 - py0 * Wn;     // multiple of 16, <= 96

    const int wm0 = (wid & 1) * 64;
    const float* in_b = in + (size_t)bb * Cn * PIX;

    // per-lane ldmatrix row byte-offsets: mi tile -> pixel m = wm0+mi*16+(lane&15)
    uint32_t pmB[4];
#pragma unroll
    for (int mi = 0; mi < 4; ++mi) {
        int m = wm0 + mi * 16 + (lane & 15);
        int x = px0 + m;
        int r = 0;
        if (x >= Wn) { x -= Wn; r = 1; }
        pmB[mi] = (uint32_t)((r * ROWXP + x + 4) * (XW * 4));
    }
    const uint32_t kHi = (uint32_t)((lane >> 4) << 4);   // +16B for k 8..15

    // zero the x-border columns xp=3 and xp=116 (all rows, all channels+pad)
    for (int e = tid; e < 2 * 4 * XW; e += TPB) {
        int side = e / (4 * XW);
        int rem  = e % (4 * XW);
        int ry   = rem / XW;
        int cw   = rem % XW;
        smem[(ry * ROWXP + (side ? 116 : 3)) * XW + cw] = 0;
    }

    float acc[4][8][4];
#pragma unroll
    for (int mi = 0; mi < 4; ++mi)
#pragma unroll
        for (int ni = 0; ni < 8; ++ni)
#pragma unroll
            for (int c = 0; c < 4; ++c) acc[mi][ni][c] = 0.f;

    // ---- stage input once, x-major channel-contiguous ----
    // unit: (cp 0..31 lane-fast, ry 0..3, x4 0..27); STS 128B-contiguous per warp
    {
#pragma unroll
        for (int i = 0; i < 28; ++i) {      // 3584 units / 128 threads
            int u   = i * TPB + tid;
            int cp  = u & 31;
            int t   = u >> 5;               // 0..111
            int x4  = t % 28;
            int ry  = t / 28;
            int y   = py0 - 1 + ry;
            float4 fa, fb;
            if ((unsigned)y < (unsigned)Hn) {
                const float* base = in_b + (size_t)(2 * cp) * PIX + y * Wn + x4 * 4;
                fa = *(const float4*)base;
                fb = *(const float4*)(base + PIX);
            } else {
                fa = make_float4(0.f, 0.f, 0.f, 0.f);
                fb = fa;
            }
            __half2 h[4] = { __floats2half2_rn(fa.x, fb.x), __floats2half2_rn(fa.y, fb.y),
                             __floats2half2_rn(fa.z, fb.z), __floats2half2_rn(fa.w, fb.w) };
#pragma unroll
            for (int j = 0; j < 4; ++j) {
                int xp = x4 * 4 + j + 4;
                smem[(ry * ROWXP + xp) * XW + cp] = *(uint32_t*)&h[j];
            }
        }
    }

    auto stage_B = [&](int tap, int buf) {
        const uint32_t* wb = g_wt + (size_t)tap * BPT;
#pragma unroll
        for (int i = 0; i < 10; ++i) {       // 1280 cpa16 / 128 threads
            int e = i * TPB + tid;
            cpa16(sbase + (SIN_W + buf * BPT + e * 4) * 4, wb + e * 4);
        }
    };

    stage_B(0, 0);
    CP_COMMIT();
    CP_WAIT0();
    __syncthreads();                  // s_in (STS) + B[0] visible to all
    stage_B(1, 1);                    // overlaps tap 0 compute
    CP_COMMIT();

#pragma unroll 1
    for (int tap = 0; tap < 9; ++tap) {
        const int dy = tap / 3, dx = tap - dy * 3;
        const uint32_t dyxB = (uint32_t)((dy * ROWXP + dx - 1) * (XW * 4));
        const uint32_t* sB = smem + SIN_W + (tap & 1) * BPT;

        // 4 k-steps of K=16 covering all 64 channels
#pragma unroll
        for (int s = 0; s < 4; ++s) {
            const uint32_t kB = kHi + (uint32_t)(s * 32);
            uint32_t af[4][4];
#pragma unroll
            for (int mi = 0; mi < 4; ++mi)
                ldsm_x4(af[mi], sbase + pmB[mi] + dyxB + kB);

            // packed B fragment: 4x LDS.128, conflict-free (20-word stride)
            const uint32_t* pb = sB + ((s * 2 + wnIdx) * 32 + lane) * 20;
            uint4 b0 = *(const uint4*)(pb + 0);
            uint4 b1 = *(const uint4*)(pb + 4);
            uint4 b2 = *(const uint4*)(pb + 8);
            uint4 b3 = *(const uint4*)(pb + 12);
            const uint32_t barr[16] = {
                b0.x, b0.y, b0.z, b0.w, b1.x, b1.y, b1.z, b1.w,
                b2.x, b2.y, b2.z, b2.w, b3.x, b3.y, b3.z, b3.w };
#pragma unroll
            for (int mi = 0; mi < 4; ++mi)
#pragma unroll
                for (int ni = 0; ni < 8; ++ni)
                    asm volatile(
                        "mma.sync.aligned.m16n8k16.row.col.f32.f16.f16.f32 "
                        "{%0,%1,%2,%3}, {%4,%5,%6,%7}, {%8,%9}, {%0,%1,%2,%3};"
                        : "+f"(acc[mi][ni][0]), "+f"(acc[mi][ni][1]),
                          "+f"(acc[mi][ni][2]), "+f"(acc[mi][ni][3])
                        : "r"(af[mi][0]), "r"(af[mi][1]),
                          "r"(af[mi][2]), "r"(af[mi][3]),
                          "r"(barr[2 * ni]), "r"(barr[2 * ni + 1]));
        }

        if (tap < 8) {
            CP_WAIT0();               // B[tap+1] landed
            __syncthreads();          // all warps done reading buf[tap&1]
            if (tap < 7) {            // refill the buffer just freed
                stage_B(tap + 2, tap & 1);
                CP_COMMIT();
            }
        }
    }

    // ---- coalesced epilogue: acc -> smem transpose -> 128B-contiguous STG ----
    float* sf = (float*)smem;            // s_out[m][n'] pitch 68 (reuses s_in)
    float* out_b = out + (size_t)bb * Fn * PIX + p0;
#pragma unroll 1
    for (int pass = 0; pass < 2; ++pass) {
        __syncthreads();                 // smem free / previous pass consumed
        if (wnIdx == pass) {
#pragma unroll
            for (int mi = 0; mi < 4; ++mi) {
                int r0 = wm0 + mi * 16 + (lane >> 2);
#pragma unroll
                for (int ni = 0; ni < 8; ++ni) {
                    int nn = ni * 8 + (lane & 3) * 2;
                    *(float2*)&sf[r0 * 68 + nn] =
                        make_float2(acc[mi][ni][0], acc[mi][ni][1]);
                    *(float2*)&sf[(r0 + 8) * 68 + nn] =
                        make_float2(acc[mi][ni][2], acc[mi][ni][3]);
                }
            }
        }
        __syncthreads();
#pragma unroll
        for (int jj = 0; jj < 16; ++jj) {
            float4 v = *(const float4*)&sf[tid * 68 + jj * 4];
            float* dst = out_b + (size_t)(pass * 64 + jj * 4) * PIX + tid;
            dst[0]               = v.x;
            dst[(size_t)PIX]     = v.y;
            dst[(size_t)2 * PIX] = v.z;
            dst[(size_t)3 * PIX] = v.w;
        }
    }
}

extern "C" void kernel_launch(void* const* d_in, const int* in_sizes, int n_in,
                              void* d_out, int out_size)
{
    (void)in_sizes; (void)n_in; (void)out_size;
    const float* in = (const float*)d_in[0];   // [32,64,112,112]
    const float* wt = (const float*)d_in[1];   // [128,64,3,3]
    float* out = (float*)d_out;                // [32,128,112,112]

    static bool attr_set = false;
    if (!attr_set) {
        cudaFuncSetAttribute(conv_hmma2_kernel,
                             cudaFuncAttributeMaxDynamicSharedMemorySize, SMEM_BYTES);
        attr_set = true;
    }
    pack_wt_h_kernel<<<(9 * BPT + 255) / 256, 256>>>(wt);
    dim3 grid(PIX / 128, 32);                  // (98, 32)
    conv_hmma2_kernel<<<grid, TPB, SMEM_BYTES>>>(in, out);
}